// round 2
// baseline (speedup 1.0000x reference)
#include <cuda_runtime.h>

// LIF spike scan: x [B=64, T=8, C=128, H=32, W=32] fp32
// Per spatial site: mem = mem*TAU + x_t; spike = (mem - THRESH) > 0; mem = (1-spike)*mem
// Output: spikes, same shape/dtype. Purely HBM-bound: 512 MiB traffic total.

#define B_DIM 64
#define T_DIM 8
#define CHW   (128 * 32 * 32)     // 131072 elements per (b, t) slab
#define CHW4  (CHW / 4)           // 32768 float4 per slab
#define NSPATIAL4 (B_DIM * CHW4)  // 2,097,152 float4 sites

__global__ __launch_bounds__(256) void lif_kernel(
    const float4* __restrict__ x, float4* __restrict__ out)
{
    const int i = blockIdx.x * blockDim.x + threadIdx.x;
    if (i >= NSPATIAL4) return;

    // i = b * CHW4 + rem  (CHW4 = 2^15 -> shifts)
    const int b   = i >> 15;
    const int rem = i & (CHW4 - 1);
    const long base = (long)b * (T_DIM * CHW4) + rem;

    // Front-batch all 8 strided loads (MLP=8, independent addresses).
    float4 xt[T_DIM];
#pragma unroll
    for (int t = 0; t < T_DIM; t++)
        xt[t] = x[base + (long)t * CHW4];

    const float TAU = 0.5f;
    const float THRESH = 1.0f;

    float4 mem = make_float4(0.f, 0.f, 0.f, 0.f);
#pragma unroll
    for (int t = 0; t < T_DIM; t++) {
        float4 s;
        mem.x = fmaf(mem.x, TAU, xt[t].x);
        mem.y = fmaf(mem.y, TAU, xt[t].y);
        mem.z = fmaf(mem.z, TAU, xt[t].z);
        mem.w = fmaf(mem.w, TAU, xt[t].w);

        s.x = (mem.x > THRESH) ? 1.0f : 0.0f;
        s.y = (mem.y > THRESH) ? 1.0f : 0.0f;
        s.z = (mem.z > THRESH) ? 1.0f : 0.0f;
        s.w = (mem.w > THRESH) ? 1.0f : 0.0f;

        // hard reset: mem = (1 - spike) * mem
        mem.x = (s.x > 0.f) ? 0.f : mem.x;
        mem.y = (s.y > 0.f) ? 0.f : mem.y;
        mem.z = (s.z > 0.f) ? 0.f : mem.z;
        mem.w = (s.w > 0.f) ? 0.f : mem.w;

        out[base + (long)t * CHW4] = s;
    }
}

extern "C" void kernel_launch(void* const* d_in, const int* in_sizes, int n_in,
                              void* d_out, int out_size)
{
    const float4* x = (const float4*)d_in[0];
    float4* out = (float4*)d_out;
    const int threads = 256;
    const int blocks = (NSPATIAL4 + threads - 1) / threads;  // 8192
    lif_kernel<<<blocks, threads>>>(x, out);
}